// round 1
// baseline (speedup 1.0000x reference)
#include <cuda_runtime.h>
#include <cstdint>

// Problem constants (fixed by setup_inputs)
#define Bn   4
#define Hn   192
#define Wn   192
#define Nn   (Hn * Wn)          // 36864
#define NG   64
#define Cc   4
#define KCAP 96
#define ETA  3.0f
#define POS_W 1.2f
#define CAP  1536               // candidate buffer per (b,g)

// Scratch (no allocations allowed)
__device__ unsigned long long g_cell_key[Bn * Nn];  // (dist_bits<<32)|g, init ~0
__device__ double g_acc[3];                          // reg, obj, cls

// ---------------------------------------------------------------------------
__global__ void k_init() {
    int i = blockIdx.x * blockDim.x + threadIdx.x;
    if (i < 3) g_acc[i] = 0.0;
    if (i < Bn * Nn) g_cell_key[i] = ~0ull;
}

// ---------------------------------------------------------------------------
// Squared distance from point (px,py) to segment P->Q (JAX seg() without sqrt)
__device__ __forceinline__ float segsq(float px, float py,
                                       float Px, float Py, float Qx, float Qy) {
    float vx = Qx - Px, vy = Qy - Py;
    float wx = px - Px, wy = py - Py;
    float t = (wx * vx + wy * vy) / (vx * vx + vy * vy + 1e-9f);
    t = fminf(fmaxf(t, 0.0f), 1.0f);
    float dx = wx - t * vx, dy = wy - t * vy;
    return dx * dx + dy * dy;
}

// One CTA per (b,g): bbox-pruned scan, exact top-96 by (dist, idx),
// reg-loss contribution + per-cell atomicMin of (dist, g).
__global__ __launch_bounds__(128) void k_main(const float* __restrict__ pred_reg,
                                              const float* __restrict__ gt_pts,
                                              const int*   __restrict__ stride_ptr) {
    const int bg = blockIdx.x;
    const int b  = bg / NG;
    const int g  = bg % NG;
    const int t  = threadIdx.x;
    const float s = stride_ptr ? (float)(*stride_ptr) : 8.0f;

    __shared__ float tri[6];
    __shared__ int   s_cnt;
    __shared__ unsigned long long s_key[CAP];
    __shared__ unsigned long long s_sel[KCAP];
    __shared__ unsigned long long s_wk[4];
    __shared__ int                s_wp[4];
    __shared__ double             s_red[4];

    if (t < 6) tri[t] = gt_pts[bg * 6 + t];
    if (t == 0) s_cnt = 0;
    __syncthreads();

    const float Ax = tri[0], Ay = tri[1];
    const float Bx = tri[2], By = tri[3];
    const float Cx = tri[4], Cy = tri[5];

    // Dilated bbox -> cell range (over-inclusive is fine; pos test filters)
    float xmin = fminf(Ax, fminf(Bx, Cx)) - ETA;
    float xmax = fmaxf(Ax, fmaxf(Bx, Cx)) + ETA;
    float ymin = fminf(Ay, fminf(By, Cy)) - ETA;
    float ymax = fmaxf(Ay, fmaxf(By, Cy)) + ETA;
    int ix0 = max(0,      (int)floorf(xmin / s - 0.5f) - 1);
    int ix1 = min(Wn - 1, (int)ceilf (xmax / s - 0.5f) + 1);
    int iy0 = max(0,      (int)floorf(ymin / s - 0.5f) - 1);
    int iy1 = min(Hn - 1, (int)ceilf (ymax / s - 0.5f) + 1);
    int bw = ix1 - ix0 + 1, bh = iy1 - iy0 + 1;
    int total = (bw > 0 && bh > 0) ? bw * bh : 0;

    for (int it = t; it < total; it += blockDim.x) {
        int ix = ix0 + it % bw;
        int iy = iy0 + it / bw;
        float px = (ix + 0.5f) * s;
        float py = (iy + 0.5f) * s;
        // sign test (inside)
        float d1 = (px - Bx) * (Ay - By) - (Ax - Bx) * (py - By);
        float d2 = (px - Cx) * (By - Cy) - (Bx - Cx) * (py - Cy);
        float d3 = (px - Ax) * (Cy - Ay) - (Cx - Ax) * (py - Ay);
        bool has_neg = (d1 < 0.f) || (d2 < 0.f) || (d3 < 0.f);
        bool has_pos = (d1 > 0.f) || (d2 > 0.f) || (d3 > 0.f);
        bool inside  = !(has_neg && has_pos);
        // min distance to edges (sqrt of min squared == min of sqrts)
        float msq = fminf(segsq(px, py, Ax, Ay, Bx, By),
                    fminf(segsq(px, py, Bx, By, Cx, Cy),
                          segsq(px, py, Cx, Cy, Ax, Ay)));
        float dist = sqrtf(msq + 1e-12f);
        if (inside || dist <= ETA) {
            int slot = atomicAdd(&s_cnt, 1);
            if (slot < CAP) {
                unsigned int db = __float_as_uint(dist);  // dist >= 0: bits monotone
                s_key[slot] = ((unsigned long long)db << 32) |
                              (unsigned int)(iy * Wn + ix);
            }
        }
    }
    __syncthreads();

    int cnt = min(s_cnt, CAP);
    const unsigned long long* sel = s_key;
    int m = cnt;
    if (cnt > KCAP) {
        m = KCAP;
        // extract the 96 smallest keys (exact (dist asc, idx asc) order)
        for (int i = 0; i < KCAP; i++) {
            unsigned long long bk = ~0ull;
            int bp = -1;
            for (int j = t; j < cnt; j += blockDim.x) {
                unsigned long long k = s_key[j];
                if (k < bk) { bk = k; bp = j; }
            }
            for (int off = 16; off; off >>= 1) {
                unsigned long long ok = __shfl_down_sync(0xffffffffu, bk, off);
                int                op = __shfl_down_sync(0xffffffffu, bp, off);
                if (ok < bk) { bk = ok; bp = op; }
            }
            if ((t & 31) == 0) { s_wk[t >> 5] = bk; s_wp[t >> 5] = bp; }
            __syncthreads();
            if (t == 0) {
                unsigned long long fb = s_wk[0]; int fp = s_wp[0];
                #pragma unroll
                for (int w2 = 1; w2 < 4; w2++)
                    if (s_wk[w2] < fb) { fb = s_wk[w2]; fp = s_wp[w2]; }
                s_sel[i] = fb;
                s_key[fp] = ~0ull;
            }
            __syncthreads();
        }
        sel = s_sel;
    }

    // Per selected candidate: reg loss + per-cell argmin-(dist,g) key
    double local = 0.0;
    if (t < m) {
        unsigned long long k = sel[t];
        unsigned int n = (unsigned int)(k & 0xffffffffu);
        unsigned int db = (unsigned int)(k >> 32);
        // cell key: lower (dist, g) wins => JAX argmin with first-g tie-break
        atomicMin(&g_cell_key[b * Nn + n],
                  ((unsigned long long)db << 32) | (unsigned int)g);

        float ax = ((float)(n % Wn) + 0.5f) * s;
        float ay = ((float)(n / Wn) + 0.5f) * s;
        float inv_s = 1.0f / s;
        float g0x = (Ax - ax) * inv_s, g0y = (Ay - ay) * inv_s;
        float g1x = (Bx - ax) * inv_s, g1y = (By - ay) * inv_s;
        float g2x = (Cx - ax) * inv_s, g2y = (Cy - ay) * inv_s;

        const float* pr = pred_reg + (size_t)b * 6 * Nn + n;
        float p0x = pr[0],        p0y = pr[(size_t)Nn];
        float p1x = pr[2*(size_t)Nn], p1y = pr[3*(size_t)Nn];
        float p2x = pr[4*(size_t)Nn], p2y = pr[5*(size_t)Nn];

        float e0x = p0x - g0x, e0y = p0y - g0y;
        float p0 = e0x * e0x + e0y * e0y;

        float dx, dy;
        dx = p1x - g1x; dy = p1y - g1y; float d11 = sqrtf(dx*dx + dy*dy + 1e-12f);
        dx = p1x - g2x; dy = p1y - g2y; float d12 = sqrtf(dx*dx + dy*dy + 1e-12f);
        dx = p2x - g1x; dy = p2y - g1y; float d21 = sqrtf(dx*dx + dy*dy + 1e-12f);
        dx = p2x - g2x; dy = p2y - g2y; float d22 = sqrtf(dx*dx + dy*dy + 1e-12f);
        // chamfer: row mins + col mins
        float cd = fminf(d11, d12) + fminf(d21, d22)
                 + fminf(d11, d21) + fminf(d12, d22);
        local = (double)p0 + (double)cd;   // LP0 = LCD = 1
    }
    // block-reduce doubles -> one atomicAdd per CTA
    for (int off = 16; off; off >>= 1)
        local += __shfl_down_sync(0xffffffffu, local, off);
    if ((t & 31) == 0) s_red[t >> 5] = local;
    __syncthreads();
    if (t == 0) {
        double v = s_red[0] + s_red[1] + s_red[2] + s_red[3];
        if (v != 0.0) atomicAdd(&g_acc[0], v);
    }
}

// ---------------------------------------------------------------------------
__global__ __launch_bounds__(256) void k_objcls(const float* __restrict__ pred_obj,
                                                const float* __restrict__ pred_cls,
                                                const int*   __restrict__ gt_lbl) {
    int i = blockIdx.x * blockDim.x + threadIdx.x;
    double obj_l = 0.0, cls_l = 0.0;
    if (i < Bn * Nn) {
        int b = i / Nn, n = i % Nn;
        unsigned long long k = g_cell_key[i];
        bool capped = (k != ~0ull);
        float x = pred_obj[i];
        // stable log-sigmoid
        float ls_pos, ls_neg;
        if (x >= 0.f) {
            float e = expf(-x);
            ls_pos = -log1pf(e);
            ls_neg = -x - log1pf(e);
        } else {
            float e = expf(x);
            ls_pos = x - log1pf(e);
            ls_neg = -log1pf(e);
        }
        obj_l = capped ? -(double)(POS_W * ls_pos) : -(double)ls_neg;

        if (capped) {
            int gg  = (int)(k & 0xffffffffu);
            int tgt = gt_lbl[b * NG + gg];
            const float* pc = pred_cls + (size_t)b * Cc * Nn + n;
            float l0 = pc[0];
            float l1 = pc[(size_t)Nn];
            float l2 = pc[2 * (size_t)Nn];
            float l3 = pc[3 * (size_t)Nn];
            float mx = fmaxf(fmaxf(l0, l1), fmaxf(l2, l3));
            float sum = expf(l0 - mx) + expf(l1 - mx) + expf(l2 - mx) + expf(l3 - mx);
            float lse = mx + logf(sum);
            float picked = (tgt == 0) ? l0 : (tgt == 1) ? l1 : (tgt == 2) ? l2 : l3;
            cls_l = (double)(lse - picked);
        }
    }
    __shared__ double s_o[8], s_c[8];
    for (int off = 16; off; off >>= 1) {
        obj_l += __shfl_down_sync(0xffffffffu, obj_l, off);
        cls_l += __shfl_down_sync(0xffffffffu, cls_l, off);
    }
    int t = threadIdx.x;
    if ((t & 31) == 0) { s_o[t >> 5] = obj_l; s_c[t >> 5] = cls_l; }
    __syncthreads();
    if (t == 0) {
        double vo = 0.0, vc = 0.0;
        #pragma unroll
        for (int w = 0; w < 8; w++) { vo += s_o[w]; vc += s_c[w]; }
        atomicAdd(&g_acc[1], vo);
        if (vc != 0.0) atomicAdd(&g_acc[2], vc);
    }
}

// ---------------------------------------------------------------------------
__global__ void k_final(float* __restrict__ out) {
    int t = threadIdx.x;
    if (t < 3) out[t] = (float)g_acc[t];
}

// ---------------------------------------------------------------------------
extern "C" void kernel_launch(void* const* d_in, const int* in_sizes, int n_in,
                              void* d_out, int out_size) {
    const float* pred_reg = (const float*)d_in[0];
    const float* pred_obj = (const float*)d_in[1];
    const float* pred_cls = (const float*)d_in[2];
    const float* gt_pts   = (const float*)d_in[3];
    const int*   gt_lbl   = (const int*)d_in[4];
    const int*   stride_p = (n_in >= 6) ? (const int*)d_in[5] : nullptr;

    k_init<<<(Bn * Nn + 255) / 256, 256>>>();
    k_main<<<Bn * NG, 128>>>(pred_reg, gt_pts, stride_p);
    k_objcls<<<(Bn * Nn + 255) / 256, 256>>>(pred_obj, pred_cls, gt_lbl);
    k_final<<<1, 32>>>((float*)d_out);
}